// round 1
// baseline (speedup 1.0000x reference)
#include <cuda_runtime.h>
#include <math.h>

// ---------------- Problem constants ----------------
#define BATCH 16384
#define NFEAT 39
#define EMB   16
#define HID   200
#define VOCABN 1000000

// ---------------- Scratch (no allocations allowed) ----------------
__device__ float g_fm[BATCH * EMB];   // FM bi-interaction output [B,16]
__device__ float g_lr[BATCH];         // LR term per row

// =====================================================================
// Kernel 1: embedding gather + FM bi-interaction + LR term
// One half-warp (16 lanes) per row; lane = embedding dim.
// =====================================================================
__global__ __launch_bounds__(256, 1) void embed_kernel(
    const int*   __restrict__ ids,   // [B,39]
    const float* __restrict__ vals,  // [B,39]
    const float* __restrict__ w,     // [VOCAB,1]
    const float* __restrict__ v)     // [VOCAB,16]
{
    const int tid = threadIdx.x;
    const int sub = tid >> 4;          // 0..15 half-warp within CTA
    const int e   = tid & 15;          // embedding dim
    const int row = blockIdx.x * 16 + sub;
    if (row >= BATCH) return;

    const int*   idp = ids  + row * NFEAT;
    const float* vp  = vals + row * NFEAT;

    float xv = 0.f, x2 = 0.f, lr = 0.f;
#pragma unroll
    for (int f = 0; f < NFEAT; ++f) {
        const int   id  = __ldg(idp + f);
        const float val = __ldg(vp + f);
        const float ve  = __ldg(v + (size_t)id * EMB + e);
        const float t   = val * ve;
        xv += t;
        x2 += t * t;                       // (val*ve)^2 == val^2 * ve^2
        if (e == 0) lr += __ldg(w + id) * val;
    }
    g_fm[row * EMB + e] = 0.5f * (xv * xv - x2);
    if (e == 0) g_lr[row] = lr;
}

// =====================================================================
// Kernel 2: fused 3-layer MLP (16->200->200->200) + rowsum + sigmoid.
// 128 rows per CTA, 256 threads.
// Thread tile: TM=8 rows x TN=13 strided cols (col = tcol + 16*j).
// One SMEM activation buffer (full layer computed in regs, then
// overwritten), weights staged in SMEM in K-chunks of 40.
// =====================================================================
#define BM   128
#define NTH  256
#define TM   8
#define TN   13
#define KB   40
#define HPAD 205   // Hs row pitch (odd-ish to break LDS bank conflicts)
#define APAD 17    // As row pitch

__global__ __launch_bounds__(NTH, 1) void mlp_kernel(
    const float* __restrict__ w0, const float* __restrict__ b0,
    const float* __restrict__ w1, const float* __restrict__ b1,
    const float* __restrict__ w2, const float* __restrict__ b2,
    const float* __restrict__ bglob,
    float*       __restrict__ out)
{
    extern __shared__ float sm[];
    float* Hs = sm;                       // [BM][HPAD]  activations
    float* Ws = Hs + BM * HPAD;           // [KB][HID]   weight chunk
    float* As = Ws + KB * HID;            // [BM][APAD]  fm tile

    const int tid  = threadIdx.x;
    const int tcol = tid & 15;            // 0..15
    const int trow = tid >> 4;            // 0..15
    const int row0 = blockIdx.x * BM;

    // Column indices for this thread (clamped; validity tracked separately)
    int  colIdx[TN];
    bool colOk[TN];
#pragma unroll
    for (int j = 0; j < TN; ++j) {
        int c = tcol + 16 * j;
        colOk[j]  = (c < HID);
        colIdx[j] = colOk[j] ? c : (HID - 1);
    }

    // ---- stage fm tile + w0 ----
    for (int idx = tid; idx < BM * EMB; idx += NTH) {
        int r = idx >> 4, e = idx & 15;
        As[r * APAD + e] = g_fm[(row0 + r) * EMB + e];
    }
    for (int idx = tid; idx < EMB * HID; idx += NTH)
        Ws[idx] = w0[idx];
    __syncthreads();

    float acc[TM][TN];

    // ---------------- Layer 0: [128,16] @ [16,200] ----------------
#pragma unroll
    for (int i = 0; i < TM; ++i)
#pragma unroll
        for (int j = 0; j < TN; ++j) acc[i][j] = 0.f;

#pragma unroll
    for (int k = 0; k < EMB; ++k) {
        float a[TM];
#pragma unroll
        for (int i = 0; i < TM; ++i) a[i] = As[(trow * TM + i) * APAD + k];
        float wt[TN];
#pragma unroll
        for (int j = 0; j < TN; ++j) wt[j] = Ws[k * HID + colIdx[j]];
#pragma unroll
        for (int i = 0; i < TM; ++i)
#pragma unroll
            for (int j = 0; j < TN; ++j) acc[i][j] += a[i] * wt[j];
    }
    __syncthreads();
    // epilogue layer 0: +bias, relu, write to Hs
    {
        float bb[TN];
#pragma unroll
        for (int j = 0; j < TN; ++j) bb[j] = colOk[j] ? __ldg(b0 + colIdx[j]) : 0.f;
#pragma unroll
        for (int i = 0; i < TM; ++i)
#pragma unroll
            for (int j = 0; j < TN; ++j)
                if (colOk[j])
                    Hs[(trow * TM + i) * HPAD + colIdx[j]] =
                        fmaxf(acc[i][j] + bb[j], 0.f);
    }
    __syncthreads();

    // ---------------- Layers 1 & 2: [128,200] @ [200,200] ----------------
#pragma unroll 1
    for (int layer = 1; layer <= 2; ++layer) {
        const float* Wg = (layer == 1) ? w1 : w2;
        const float* bg = (layer == 1) ? b1 : b2;

#pragma unroll
        for (int i = 0; i < TM; ++i)
#pragma unroll
            for (int j = 0; j < TN; ++j) acc[i][j] = 0.f;

#pragma unroll 1
        for (int k0 = 0; k0 < HID; k0 += KB) {
            // stage weight chunk [KB][HID] (float4 coalesced)
            const float4* src = (const float4*)(Wg + k0 * HID);
            float4*       dst = (float4*)Ws;
            for (int idx = tid; idx < (KB * HID) / 4; idx += NTH)
                dst[idx] = __ldg(src + idx);
            __syncthreads();

#pragma unroll 4
            for (int kk = 0; kk < KB; ++kk) {
                const int k = k0 + kk;
                float a[TM];
#pragma unroll
                for (int i = 0; i < TM; ++i)
                    a[i] = Hs[(trow * TM + i) * HPAD + k];
                float wt[TN];
#pragma unroll
                for (int j = 0; j < TN; ++j)
                    wt[j] = Ws[kk * HID + colIdx[j]];
#pragma unroll
                for (int i = 0; i < TM; ++i)
#pragma unroll
                    for (int j = 0; j < TN; ++j)
                        acc[i][j] += a[i] * wt[j];
            }
            __syncthreads();
        }

        // epilogue: +bias, relu, overwrite Hs
        float bb[TN];
#pragma unroll
        for (int j = 0; j < TN; ++j) bb[j] = colOk[j] ? __ldg(bg + colIdx[j]) : 0.f;
        __syncthreads();   // all reads of Hs done before overwrite
#pragma unroll
        for (int i = 0; i < TM; ++i)
#pragma unroll
            for (int j = 0; j < TN; ++j)
                if (colOk[j])
                    Hs[(trow * TM + i) * HPAD + colIdx[j]] =
                        fmaxf(acc[i][j] + bb[j], 0.f);
        __syncthreads();
    }

    // ---------------- Row-sum + LR + sigmoid ----------------
    // 2 threads per row: thread sums 100 cols each, shfl-combine.
    {
        const int r  = tid >> 1;
        const int c0 = (tid & 1) * 100;
        float s = 0.f;
#pragma unroll 4
        for (int c = 0; c < 100; ++c) s += Hs[r * HPAD + c0 + c];
        s += __shfl_down_sync(0xffffffffu, s, 1);
        if ((tid & 1) == 0) {
            const int gr = row0 + r;
            const float x = g_lr[gr] + __ldg(bglob) + s;
            out[gr] = 1.f / (1.f + expf(-x));
        }
    }
}

// =====================================================================
// Launch
// =====================================================================
extern "C" void kernel_launch(void* const* d_in, const int* in_sizes, int n_in,
                              void* d_out, int out_size)
{
    const int*   feat_ids  = (const int*)  d_in[0];
    const float* feat_vals = (const float*)d_in[1];
    const float* w         = (const float*)d_in[2];
    const float* v         = (const float*)d_in[3];
    const float* b         = (const float*)d_in[4];
    const float* w0        = (const float*)d_in[5];
    const float* b0        = (const float*)d_in[6];
    const float* w1        = (const float*)d_in[7];
    const float* b1        = (const float*)d_in[8];
    const float* w2        = (const float*)d_in[9];
    const float* b2        = (const float*)d_in[10];
    float* out = (float*)d_out;

    embed_kernel<<<BATCH / 16, 256>>>(feat_ids, feat_vals, w, v);

    const int smem_bytes = (BM * HPAD + KB * HID + BM * APAD) * (int)sizeof(float);
    static bool attr_set = false;
    if (!attr_set) {
        cudaFuncSetAttribute(mlp_kernel,
                             cudaFuncAttributeMaxDynamicSharedMemorySize,
                             smem_bytes);
        attr_set = true;
    }
    mlp_kernel<<<BATCH / BM, NTH, smem_bytes>>>(w0, b0, w1, b1, w2, b2, b, out);
}

// round 3
// speedup vs baseline: 1.1995x; 1.1995x over previous
#include <cuda_runtime.h>
#include <math.h>

// ---------------- Problem constants ----------------
#define BATCH 16384
#define NFEAT 39
#define EMB   16
#define HID   200

// ---------------- Scratch ----------------
__device__ float g_fm[BATCH * EMB];
__device__ float g_lr[BATCH];

// =====================================================================
// Kernel 1: embedding gather + FM bi-interaction + LR term
// =====================================================================
__global__ __launch_bounds__(256, 1) void embed_kernel(
    const int*   __restrict__ ids,
    const float* __restrict__ vals,
    const float* __restrict__ w,
    const float* __restrict__ v)
{
    const int tid = threadIdx.x;
    const int sub = tid >> 4;
    const int e   = tid & 15;
    const int row = blockIdx.x * 16 + sub;
    if (row >= BATCH) return;

    const int*   idp = ids  + row * NFEAT;
    const float* vp  = vals + row * NFEAT;

    float xv = 0.f, x2 = 0.f, lr = 0.f;
#pragma unroll
    for (int f = 0; f < NFEAT; ++f) {
        const int   id  = __ldg(idp + f);
        const float val = __ldg(vp + f);
        const float ve  = __ldg(v + (size_t)id * EMB + e);
        const float t   = val * ve;
        xv += t;
        x2 += t * t;
        if (e == 0) lr += __ldg(w + id) * val;
    }
    g_fm[row * EMB + e] = 0.5f * (xv * xv - x2);
    if (e == 0) g_lr[row] = lr;
}

// =====================================================================
// Kernel 2: fused MLP with packed f32x2 FFMA.
// 128 rows/CTA, 256 threads (16x16 thread grid).
// Each thread: 4 row-PAIRS (f32x2) x 13 strided cols = 52 f32x2 accs.
// Activations column-major in SMEM: Hs[col][row], pitch 130 (even).
// Weight chunks double-buffered via cp.async.
// =====================================================================
#define BM    128
#define NTH   256
#define NPAIR 4          // 8 rows as 4 f32x2 pairs
#define TN    13
#define KB    40
#define RPITCH 130       // row pitch for column-major activations (even!)

// ---- f32x2 helpers ----
__device__ __forceinline__ void ffma2(unsigned long long& d,
                                      unsigned long long a,
                                      unsigned long long b)
{
    asm("fma.rn.f32x2 %0, %1, %2, %0;" : "+l"(d) : "l"(a), "l"(b));
}
__device__ __forceinline__ unsigned long long dup2(unsigned x)
{
    unsigned long long r;
    asm("mov.b64 %0, {%1, %1};" : "=l"(r) : "r"(x));
    return r;
}
__device__ __forceinline__ void unpack2(unsigned long long p, float& lo, float& hi)
{
    unsigned a, b;
    asm("mov.b64 {%0, %1}, %2;" : "=r"(a), "=r"(b) : "l"(p));
    lo = __uint_as_float(a);
    hi = __uint_as_float(b);
}
__device__ __forceinline__ void cp16(void* smem_dst, const void* gsrc)
{
    unsigned s = (unsigned)__cvta_generic_to_shared(smem_dst);
    asm volatile("cp.async.cg.shared.global [%0], [%1], 16;" :: "r"(s), "l"(gsrc));
}
__device__ __forceinline__ void cp_commit()  { asm volatile("cp.async.commit_group;"); }
__device__ __forceinline__ void cp_wait0()   { asm volatile("cp.async.wait_group 0;"); }
__device__ __forceinline__ void cp_wait1()   { asm volatile("cp.async.wait_group 1;"); }

__global__ __launch_bounds__(NTH, 1) void mlp_kernel(
    const float* __restrict__ w0, const float* __restrict__ b0,
    const float* __restrict__ w1, const float* __restrict__ b1,
    const float* __restrict__ w2, const float* __restrict__ b2,
    const float* __restrict__ bglob,
    float*       __restrict__ out)
{
    extern __shared__ float sm[];
    float* Hs  = sm;                        // [HID][RPITCH] col-major activations
    float* Wb0 = Hs  + HID * RPITCH;        // [KB][HID] weight buffer 0
    float* Wb1 = Wb0 + KB * HID;            // [KB][HID] weight buffer 1
    float* As  = Wb1 + KB * HID;            // [EMB][RPITCH] fm tile, col-major

    const int tid  = threadIdx.x;
    const int tcol = tid & 15;
    const int trow = tid >> 4;              // 0..15 -> rows trow*8 .. +7
    const int row0 = blockIdx.x * BM;
    const int rbase = trow * 8;

    int  colIdx[TN];
    bool colOk[TN];
#pragma unroll
    for (int j = 0; j < TN; ++j) {
        int c = tcol + 16 * j;
        colOk[j]  = (c < HID);
        colIdx[j] = colOk[j] ? c : (HID - 1);
    }

    // ---- stage w0 (3200 floats) into Wb0, then prefetch w1 chunk0 into Wb1 ----
    for (int idx = tid; idx < (EMB * HID) / 4; idx += NTH)
        cp16(Wb0 + idx * 4, w0 + idx * 4);
    cp_commit();
    for (int idx = tid; idx < (KB * HID) / 4; idx += NTH)
        cp16(Wb1 + idx * 4, w1 + idx * 4);
    cp_commit();

    // ---- stage fm tile into As (transpose to col-major) ----
    for (int idx = tid; idx < BM * EMB; idx += NTH) {
        int r = idx >> 4, e = idx & 15;
        As[e * RPITCH + r] = g_fm[(row0 + r) * EMB + e];
    }
    cp_wait1();            // w0 ready (w1 chunk may still be in flight)
    __syncthreads();

    unsigned long long acc[NPAIR][TN];

    // ================= Layer 0: [128,16] @ [16,200] =================
#pragma unroll
    for (int i = 0; i < NPAIR; ++i)
#pragma unroll
        for (int j = 0; j < TN; ++j) acc[i][j] = 0ull;

#pragma unroll 4
    for (int k = 0; k < EMB; ++k) {
        unsigned long long a[NPAIR];
#pragma unroll
        for (int i = 0; i < NPAIR; ++i)
            a[i] = *(const unsigned long long*)&As[k * RPITCH + rbase + 2 * i];
        unsigned long long wd[TN];
#pragma unroll
        for (int j = 0; j < TN; ++j)
            wd[j] = dup2(*(const unsigned*)&Wb0[k * HID + colIdx[j]]);
#pragma unroll
        for (int i = 0; i < NPAIR; ++i)
#pragma unroll
            for (int j = 0; j < TN; ++j) ffma2(acc[i][j], a[i], wd[j]);
    }
    cp_wait0();            // w1 chunk0 landed
    __syncthreads();       // all reads of As done; Wb1 visible to all

    // epilogue L0: bias + relu -> Hs (col-major)
    {
#pragma unroll
        for (int j = 0; j < TN; ++j) {
            if (!colOk[j]) continue;
            const float bb = __ldg(b0 + colIdx[j]);
#pragma unroll
            for (int i = 0; i < NPAIR; ++i) {
                float lo, hi; unpack2(acc[i][j], lo, hi);
                float2 st;
                st.x = fmaxf(lo + bb, 0.f);
                st.y = fmaxf(hi + bb, 0.f);
                *(float2*)&Hs[colIdx[j] * RPITCH + rbase + 2 * i] = st;
            }
        }
    }
    __syncthreads();

    // ================= Layers 1 & 2: [128,200] @ [200,200] =================
    float rsum[8];         // final row sums (layer 2 only)
#pragma unroll
    for (int i = 0; i < 8; ++i) rsum[i] = 0.f;

    float* Wcur = Wb1;     // layer-1 chunk0 already staged
    float* Wnxt = Wb0;

#pragma unroll 1
    for (int layer = 1; layer <= 2; ++layer) {
        const float* Wg = (layer == 1) ? w1 : w2;
        const float* bg = (layer == 1) ? b1 : b2;

#pragma unroll
        for (int i = 0; i < NPAIR; ++i)
#pragma unroll
            for (int j = 0; j < TN; ++j) acc[i][j] = 0ull;

#pragma unroll 1
        for (int c = 0; c < HID / KB; ++c) {
            // prefetch next chunk (or next layer's chunk0) into Wnxt
            const float* nsrc = nullptr;
            if (c + 1 < HID / KB)       nsrc = Wg + (c + 1) * KB * HID;
            else if (layer == 1)        nsrc = w2;
            if (nsrc) {
                for (int idx = tid; idx < (KB * HID) / 4; idx += NTH)
                    cp16(Wnxt + idx * 4, nsrc + idx * 4);
                cp_commit();
            }

            // compute current chunk
#pragma unroll 2
            for (int kk = 0; kk < KB; ++kk) {
                const int k = c * KB + kk;
                unsigned long long a[NPAIR];
#pragma unroll
                for (int i = 0; i < NPAIR; ++i)
                    a[i] = *(const unsigned long long*)&Hs[k * RPITCH + rbase + 2 * i];
                unsigned long long wd[TN];
#pragma unroll
                for (int j = 0; j < TN; ++j)
                    wd[j] = dup2(*(const unsigned*)&Wcur[kk * HID + colIdx[j]]);
#pragma unroll
                for (int i = 0; i < NPAIR; ++i)
#pragma unroll
                    for (int j = 0; j < TN; ++j) ffma2(acc[i][j], a[i], wd[j]);
            }

            cp_wait0();
            __syncthreads();
            float* t = Wcur; Wcur = Wnxt; Wnxt = t;
        }

        if (layer == 1) {
            // epilogue L1: bias + relu -> Hs (overwrite; reads finished at last sync)
#pragma unroll
            for (int j = 0; j < TN; ++j) {
                if (!colOk[j]) continue;
                const float bb = __ldg(bg + colIdx[j]);
#pragma unroll
                for (int i = 0; i < NPAIR; ++i) {
                    float lo, hi; unpack2(acc[i][j], lo, hi);
                    float2 st;
                    st.x = fmaxf(lo + bb, 0.f);
                    st.y = fmaxf(hi + bb, 0.f);
                    *(float2*)&Hs[colIdx[j] * RPITCH + rbase + 2 * i] = st;
                }
            }
            __syncthreads();
        } else {
            // epilogue L2: bias + relu + row-sum kept in registers
#pragma unroll
            for (int j = 0; j < TN; ++j) {
                if (!colOk[j]) continue;
                const float bb = __ldg(bg + colIdx[j]);
#pragma unroll
                for (int i = 0; i < NPAIR; ++i) {
                    float lo, hi; unpack2(acc[i][j], lo, hi);
                    rsum[2 * i]     += fmaxf(lo + bb, 0.f);
                    rsum[2 * i + 1] += fmaxf(hi + bb, 0.f);
                }
            }
        }
    }

    // ---- reduce row sums across the 16 tcol lanes (within half-warp) ----
#pragma unroll
    for (int off = 8; off >= 1; off >>= 1)
#pragma unroll
        for (int i = 0; i < 8; ++i)
            rsum[i] += __shfl_down_sync(0xffffffffu, rsum[i], off, 16);

    if (tcol == 0) {
        const float bb = __ldg(bglob);
#pragma unroll
        for (int i = 0; i < 8; ++i) {
            const int gr = row0 + rbase + i;
            const float x = g_lr[gr] + bb + rsum[i];
            out[gr] = 1.f / (1.f + expf(-x));
        }
    }
}

// =====================================================================
// Launch
// =====================================================================
extern "C" void kernel_launch(void* const* d_in, const int* in_sizes, int n_in,
                              void* d_out, int out_size)
{
    const int*   feat_ids  = (const int*)  d_in[0];
    const float* feat_vals = (const float*)d_in[1];
    const float* w         = (const float*)d_in[2];
    const float* v         = (const float*)d_in[3];
    const float* b         = (const float*)d_in[4];
    const float* w0        = (const float*)d_in[5];
    const float* b0        = (const float*)d_in[6];
    const float* w1        = (const float*)d_in[7];
    const float* b1        = (const float*)d_in[8];
    const float* w2        = (const float*)d_in[9];
    const float* b2        = (const float*)d_in[10];
    float* out = (float*)d_out;

    embed_kernel<<<BATCH / 16, 256>>>(feat_ids, feat_vals, w, v);

    const int smem_bytes = (HID * RPITCH + 2 * KB * HID + EMB * RPITCH)
                           * (int)sizeof(float);
    static bool attr_set = false;
    if (!attr_set) {
        cudaFuncSetAttribute(mlp_kernel,
                             cudaFuncAttributeMaxDynamicSharedMemorySize,
                             smem_bytes);
        attr_set = true;
    }
    mlp_kernel<<<BATCH / BM, NTH, smem_bytes>>>(w0, b0, w1, b1, w2, b2, b, out);
}

// round 7
// speedup vs baseline: 1.6436x; 1.3702x over previous
#include <cuda_runtime.h>
#include <cuda_bf16.h>
#include <math.h>
#include <stdint.h>

// ---------------- Problem constants ----------------
#define BATCH 16384
#define NFEAT 39
#define EMB   16
#define HID   200
#define NPAD  208          // padded N (and K) for 16/8 tiling
#define KPG   224          // gmem k-pitch of prepped weights (bf16 elems)

// ---------------- Scratch ----------------
__device__ float g_fm[BATCH * EMB];
__device__ float g_lr[BATCH];
// Prepped transposed split weights: [3 layers][208 n][224 k] bf16, zero-padded
__device__ __nv_bfloat16 g_wt_hi[3 * NPAD * KPG];
__device__ __nv_bfloat16 g_wt_lo[3 * NPAD * KPG];

// =====================================================================
// Helpers
// =====================================================================
__device__ __forceinline__ uint32_t smem_u32(const void* p) {
    uint32_t a;
    asm("{ .reg .u64 t; cvta.to.shared.u64 t, %1; cvt.u32.u64 %0, t; }"
        : "=r"(a) : "l"(p));
    return a;
}
__device__ __forceinline__ void cp16(uint32_t smem_dst, const void* gsrc) {
    asm volatile("cp.async.cg.shared.global [%0], [%1], 16;"
                 :: "r"(smem_dst), "l"(gsrc));
}
__device__ __forceinline__ void cp_commit() { asm volatile("cp.async.commit_group;"); }
__device__ __forceinline__ void cp_wait0()  { asm volatile("cp.async.wait_group 0;"); }
__device__ __forceinline__ void cp_wait1()  { asm volatile("cp.async.wait_group 1;"); }

__device__ __forceinline__ void ldsm4(uint32_t addr, uint32_t* r) {
    asm volatile("ldmatrix.sync.aligned.m8n8.x4.shared.b16 {%0,%1,%2,%3}, [%4];"
                 : "=r"(r[0]), "=r"(r[1]), "=r"(r[2]), "=r"(r[3]) : "r"(addr));
}
__device__ __forceinline__ void mma16816(float* c, const uint32_t* a,
                                         uint32_t b0, uint32_t b1) {
    asm volatile("mma.sync.aligned.m16n8k16.row.col.f32.bf16.bf16.f32 "
                 "{%0,%1,%2,%3}, {%4,%5,%6,%7}, {%8,%9}, {%0,%1,%2,%3};"
                 : "+f"(c[0]), "+f"(c[1]), "+f"(c[2]), "+f"(c[3])
                 : "r"(a[0]), "r"(a[1]), "r"(a[2]), "r"(a[3]),
                   "r"(b0), "r"(b1));
}
__device__ __forceinline__ void split_pack(float x0, float x1,
                                           unsigned& wh, unsigned& wl) {
    __nv_bfloat16 h0 = __float2bfloat16_rn(x0);
    __nv_bfloat16 h1 = __float2bfloat16_rn(x1);
    float r0 = x0 - __bfloat162float(h0);
    float r1 = x1 - __bfloat162float(h1);
    __nv_bfloat16 l0 = __float2bfloat16_rn(r0);
    __nv_bfloat16 l1 = __float2bfloat16_rn(r1);
    wh = ((unsigned)__bfloat16_as_ushort(h1) << 16) | __bfloat16_as_ushort(h0);
    wl = ((unsigned)__bfloat16_as_ushort(l1) << 16) | __bfloat16_as_ushort(l0);
}

// =====================================================================
// Kernel 1: embedding/FM/LR (blocks 0..1023) + weight prep (blocks 1024+)
// =====================================================================
#define EMB_BLOCKS 1024
#define PREP_ITEMS (3 * NPAD * (KPG / 2))     // (l, n, kpair) items = 69888
#define PREP_BLOCKS ((PREP_ITEMS + 255) / 256) // 273

__global__ __launch_bounds__(256, 1) void embed_prep_kernel(
    const int*   __restrict__ ids,
    const float* __restrict__ vals,
    const float* __restrict__ w,
    const float* __restrict__ v,
    const float* __restrict__ w0,
    const float* __restrict__ w1,
    const float* __restrict__ w2)
{
    const int tid = threadIdx.x;
    if (blockIdx.x < EMB_BLOCKS) {
        const int sub = tid >> 4;
        const int e   = tid & 15;
        const int row = blockIdx.x * 16 + sub;

        const int*   idp = ids  + row * NFEAT;
        const float* vp  = vals + row * NFEAT;

        float xv = 0.f, x2 = 0.f, lr = 0.f;
#pragma unroll
        for (int f = 0; f < NFEAT; ++f) {
            const int   id  = __ldg(idp + f);
            const float val = __ldg(vp + f);
            const float ve  = __ldg(v + (size_t)id * EMB + e);
            const float t   = val * ve;
            xv += t;
            x2 += t * t;
            if (e == 0) lr += __ldg(w + id) * val;
        }
        g_fm[row * EMB + e] = 0.5f * (xv * xv - x2);
        if (e == 0) g_lr[row] = lr;
    } else {
        // weight prep: transpose + split into g_wt_hi/lo
        const int g = (blockIdx.x - EMB_BLOCKS) * 256 + tid;
        if (g >= PREP_ITEMS) return;
        const int l   = g / (NPAD * (KPG / 2));
        const int rem = g - l * (NPAD * (KPG / 2));
        const int n   = rem / (KPG / 2);
        const int kp  = rem - n * (KPG / 2);
        const int k   = 2 * kp;
        const int Kl  = (l == 0) ? EMB : HID;
        const float* W = (l == 0) ? w0 : (l == 1) ? w1 : w2;
        float x0 = 0.f, x1 = 0.f;
        if (n < HID) {
            if (k     < Kl) x0 = __ldg(W + (size_t)k       * HID + n);
            if (k + 1 < Kl) x1 = __ldg(W + (size_t)(k + 1) * HID + n);
        }
        unsigned wh, wl;
        split_pack(x0, x1, wh, wl);
        const size_t di = ((size_t)l * NPAD + n) * KPG + k;   // even -> 4B aligned
        *(unsigned*)((char*)g_wt_hi + di * 2) = wh;
        *(unsigned*)((char*)g_wt_lo + di * 2) = wl;
    }
}

// =====================================================================
// Kernel 2: split-bf16 mma.sync MLP. 128 rows/CTA, 256 threads (8 warps).
// Warp w owns rows w*16..+15, all 208 cols: 26 m16n8 tiles, 104 f32 accs.
// =====================================================================
#define NTH2 256
#define APB  464                 // As row pitch in bytes (232 bf16)
#define WPB  80                  // Wc row pitch in bytes (40 bf16)
#define AS_H 0
#define AS_L (128 * APB)                     // 59392
#define WC_O (2 * 128 * APB)                 // 118784
#define WC_SZ (NPAD * WPB)                   // 16640 per buffer-half
#define BIAS_O (WC_O + 4 * WC_SZ)            // 185344
#define SMEM_TOT (BIAS_O + 3 * NPAD * 4)     // 187840

__global__ __launch_bounds__(NTH2, 1) void mlp_mma_kernel(
    const float* __restrict__ b0,
    const float* __restrict__ b1,
    const float* __restrict__ b2,
    const float* __restrict__ bglob,
    float*       __restrict__ out)
{
    extern __shared__ char smem[];
    const uint32_t SB = smem_u32(smem);
    float* bias_s = (float*)(smem + BIAS_O);

    const int tid  = threadIdx.x;
    const int wid  = tid >> 5;
    const int lane = tid & 31;
    const int row0 = blockIdx.x * 128;

    // ---- weight chunk prefetch helper (stage s -> (layer, chunk)) ----
    auto stage_lc = [](int s, int& l, int& c) {
        if (s == 0)      { l = 0; c = 0; }
        else if (s <= 7) { l = 1; c = s - 1; }
        else             { l = 2; c = s - 8; }
    };
    auto prefetch = [&](int s, int buf) {
        int l, c; stage_lc(s, l, c);
        const char* srcH = (const char*)g_wt_hi + ((size_t)l * NPAD * KPG + c * 32) * 2;
        const char* srcL = (const char*)g_wt_lo + ((size_t)l * NPAD * KPG + c * 32) * 2;
        const uint32_t dH = SB + WC_O + (uint32_t)(buf * 2 + 0) * WC_SZ;
        const uint32_t dL = SB + WC_O + (uint32_t)(buf * 2 + 1) * WC_SZ;
        for (int idx = tid; idx < NPAD * 4; idx += NTH2) {
            const int r = idx >> 2, sg = idx & 3;
            cp16(dH + r * WPB + sg * 16, srcH + (size_t)r * (KPG * 2) + sg * 16);
            cp16(dL + r * WPB + sg * 16, srcL + (size_t)r * (KPG * 2) + sg * 16);
        }
        cp_commit();
    };

    // ---- kick off first two weight chunks ----
    prefetch(0, 0);
    prefetch(1, 1);

    // ---- init: bias, A-pad zero, L0 activations (split fm -> As) ----
    for (int i = tid; i < 3 * NPAD; i += NTH2) {
        const int l = i / NPAD, n = i - l * NPAD;
        const float* bp = (l == 0) ? b0 : (l == 1) ? b1 : b2;
        bias_s[i] = (n < HID) ? __ldg(bp + n) : 0.f;
    }
    for (int i = tid; i < 128 * 8; i += NTH2) {   // zero k=208..223
        const int r = i >> 3, q = i & 7;
        *(unsigned*)(smem + AS_H + r * APB + 416 + q * 4) = 0u;
        *(unsigned*)(smem + AS_L + r * APB + 416 + q * 4) = 0u;
    }
    {
        const int r  = tid >> 1;
        const int hh = tid & 1;
        const float* src = g_fm + (size_t)(row0 + r) * EMB + hh * 8;
#pragma unroll
        for (int q = 0; q < 4; ++q) {
            unsigned wh, wl;
            split_pack(src[2 * q], src[2 * q + 1], wh, wl);
            *(unsigned*)(smem + AS_H + r * APB + hh * 16 + q * 4) = wh;
            *(unsigned*)(smem + AS_L + r * APB + hh * 16 + q * 4) = wl;
        }
    }

    float acc[26][4];
    float rs1 = 0.f, rs2 = 0.f;

    // lane-derived ldmatrix address components
    const uint32_t arow = (uint32_t)(wid * 16 + (lane & 15));
    const uint32_t akofs = (uint32_t)((lane >> 4) << 3);
    const uint32_t brow = (uint32_t)((lane & 7) + ((lane >> 4) << 3));
    const uint32_t bkofs = (uint32_t)(((lane >> 3) & 1) << 3);

#pragma unroll 1
    for (int s = 0; s < 15; ++s) {
        int l, c; stage_lc(s, l, c);

        if (s == 0 || s == 1 || s == 8) {
#pragma unroll
            for (int t = 0; t < 26; ++t)
#pragma unroll
                for (int q = 0; q < 4; ++q) acc[t][q] = 0.f;
        }

        if (s == 14) cp_wait0(); else cp_wait1();
        __syncthreads();

        const int buf = s & 1;
        const uint32_t wbh = SB + WC_O + (uint32_t)(buf * 2 + 0) * WC_SZ;
        const uint32_t wbl = SB + WC_O + (uint32_t)(buf * 2 + 1) * WC_SZ;
        const int ksteps = (l == 0) ? 1 : 2;

#pragma unroll 1
        for (int ks = 0; ks < ksteps; ++ks) {
            const uint32_t kA = (uint32_t)((l == 0 ? 0 : c * 32) + ks * 16);
            uint32_t ah[4], al[4];
            ldsm4(SB + AS_H + arow * APB + (kA + akofs) * 2, ah);
            ldsm4(SB + AS_L + arow * APB + (kA + akofs) * 2, al);
            const uint32_t bko = (uint32_t)(ks * 16) + bkofs;
            const uint32_t bhA = wbh + brow * WPB + bko * 2;
            const uint32_t blA = wbl + brow * WPB + bko * 2;
#pragma unroll
            for (int ntp = 0; ntp < 13; ++ntp) {
                uint32_t bh[4], bl[4];
                ldsm4(bhA + ntp * (16 * WPB), bh);
                ldsm4(blA + ntp * (16 * WPB), bl);
                mma16816(acc[2 * ntp],     ah, bh[0], bh[1]);
                mma16816(acc[2 * ntp],     ah, bl[0], bl[1]);
                mma16816(acc[2 * ntp],     al, bh[0], bh[1]);
                mma16816(acc[2 * ntp + 1], ah, bh[2], bh[3]);
                mma16816(acc[2 * ntp + 1], ah, bl[2], bl[3]);
                mma16816(acc[2 * ntp + 1], al, bh[2], bh[3]);
            }
        }
        __syncthreads();                 // all warps done reading buf / As

        if (s + 2 <= 14) prefetch(s + 2, buf);

        // ---- layer-end epilogues ----
        if (s == 0 || s == 7) {          // ReLU + re-split into As
            const int lb = (s == 0) ? 0 : 1;
            const int r1 = wid * 16 + (lane >> 2);
#pragma unroll
            for (int ntp = 0; ntp < 13; ++ntp)
#pragma unroll
                for (int sub = 0; sub < 2; ++sub) {
                    const int nt = 2 * ntp + sub;
                    const int n  = ntp * 16 + sub * 8 + 2 * (lane & 3);
                    const float bb0 = bias_s[lb * NPAD + n];
                    const float bb1 = bias_s[lb * NPAD + n + 1];
                    unsigned wh, wl;
                    split_pack(fmaxf(acc[nt][0] + bb0, 0.f),
                               fmaxf(acc[nt][1] + bb1, 0.f), wh, wl);
                    *(unsigned*)(smem + AS_H + r1 * APB + 2 * n) = wh;
                    *(unsigned*)(smem + AS_L + r1 * APB + 2 * n) = wl;
                    split_pack(fmaxf(acc[nt][2] + bb0, 0.f),
                               fmaxf(acc[nt][3] + bb1, 0.f), wh, wl);
                    *(unsigned*)(smem + AS_H + (r1 + 8) * APB + 2 * n) = wh;
                    *(unsigned*)(smem + AS_L + (r1 + 8) * APB + 2 * n) = wl;
                }
        } else if (s == 14) {            // ReLU + row-sum
#pragma unroll
            for (int ntp = 0; ntp < 13; ++ntp)
#pragma unroll
                for (int sub = 0; sub < 2; ++sub) {
                    const int nt = 2 * ntp + sub;
                    const int n  = ntp * 16 + sub * 8 + 2 * (lane & 3);
                    const float bb0 = bias_s[2 * NPAD + n];
                    const float bb1 = bias_s[2 * NPAD + n + 1];
                    rs1 += fmaxf(acc[nt][0] + bb0, 0.f) + fmaxf(acc[nt][1] + bb1, 0.f);
                    rs2 += fmaxf(acc[nt][2] + bb0, 0.f) + fmaxf(acc[nt][3] + bb1, 0.f);
                }
        }
    }

    // ---- reduce within 4-lane groups; rows r1 = wid*16 + lane/4, r2 = +8 ----
    rs1 += __shfl_xor_sync(0xffffffffu, rs1, 1);
    rs1 += __shfl_xor_sync(0xffffffffu, rs1, 2);
    rs2 += __shfl_xor_sync(0xffffffffu, rs2, 1);
    rs2 += __shfl_xor_sync(0xffffffffu, rs2, 2);
    if ((lane & 3) == 0) {
        const float bb = __ldg(bglob);
        const int r1 = row0 + wid * 16 + (lane >> 2);
        const float x1 = g_lr[r1] + bb + rs1;
        out[r1] = 1.f / (1.f + expf(-x1));
        const int r2 = r1 + 8;
        const float x2 = g_lr[r2] + bb + rs2;
        out[r2] = 1.f / (1.f + expf(-x2));
    }
}

// =====================================================================
// Launch
// =====================================================================
extern "C" void kernel_launch(void* const* d_in, const int* in_sizes, int n_in,
                              void* d_out, int out_size)
{
    const int*   feat_ids  = (const int*)  d_in[0];
    const float* feat_vals = (const float*)d_in[1];
    const float* w         = (const float*)d_in[2];
    const float* v         = (const float*)d_in[3];
    const float* b         = (const float*)d_in[4];
    const float* w0        = (const float*)d_in[5];
    const float* b0        = (const float*)d_in[6];
    const float* w1        = (const float*)d_in[7];
    const float* b1        = (const float*)d_in[8];
    const float* w2        = (const float*)d_in[9];
    const float* b2        = (const float*)d_in[10];
    float* out = (float*)d_out;

    embed_prep_kernel<<<EMB_BLOCKS + PREP_BLOCKS, 256>>>(
        feat_ids, feat_vals, w, v, w0, w1, w2);

    static bool attr_set = false;
    if (!attr_set) {
        cudaFuncSetAttribute(mlp_mma_kernel,
                             cudaFuncAttributeMaxDynamicSharedMemorySize,
                             SMEM_TOT);
        attr_set = true;
    }
    mlp_mma_kernel<<<BATCH / 128, NTH2, SMEM_TOT>>>(b0, b1, b2, b, out);
}

// round 8
// speedup vs baseline: 1.7034x; 1.0364x over previous
#include <cuda_runtime.h>
#include <cuda_bf16.h>
#include <math.h>
#include <stdint.h>

// ---------------- Problem constants ----------------
#define BATCH 16384
#define NFEAT 39
#define EMB   16
#define HID   200
#define NPAD  208          // padded N (and K) for 16/8 tiling
#define KPG   224          // gmem k-pitch of prepped weights (bf16 elems)

// ---------------- Scratch ----------------
__device__ float g_fm[BATCH * EMB];
__device__ float g_lr[BATCH];
// Prepped transposed split weights: [3 layers][208 n][224 k] bf16, zero-padded
__device__ __nv_bfloat16 g_wt_hi[3 * NPAD * KPG];
__device__ __nv_bfloat16 g_wt_lo[3 * NPAD * KPG];

// =====================================================================
// Helpers
// =====================================================================
__device__ __forceinline__ uint32_t smem_u32(const void* p) {
    uint32_t a;
    asm("{ .reg .u64 t; cvta.to.shared.u64 t, %1; cvt.u32.u64 %0, t; }"
        : "=r"(a) : "l"(p));
    return a;
}
__device__ __forceinline__ void cp16(uint32_t smem_dst, const void* gsrc) {
    asm volatile("cp.async.cg.shared.global [%0], [%1], 16;"
                 :: "r"(smem_dst), "l"(gsrc));
}
__device__ __forceinline__ void cp_commit() { asm volatile("cp.async.commit_group;"); }
__device__ __forceinline__ void cp_wait0()  { asm volatile("cp.async.wait_group 0;"); }
__device__ __forceinline__ void cp_wait1()  { asm volatile("cp.async.wait_group 1;"); }

__device__ __forceinline__ void ldsm4(uint32_t addr, uint32_t* r) {
    asm volatile("ldmatrix.sync.aligned.m8n8.x4.shared.b16 {%0,%1,%2,%3}, [%4];"
                 : "=r"(r[0]), "=r"(r[1]), "=r"(r[2]), "=r"(r[3]) : "r"(addr));
}
__device__ __forceinline__ void ldsm2(uint32_t addr, uint32_t* r) {
    asm volatile("ldmatrix.sync.aligned.m8n8.x2.shared.b16 {%0,%1}, [%2];"
                 : "=r"(r[0]), "=r"(r[1]) : "r"(addr));
}
__device__ __forceinline__ void mma16816(float* c, const uint32_t* a,
                                         uint32_t b0, uint32_t b1) {
    asm volatile("mma.sync.aligned.m16n8k16.row.col.f32.bf16.bf16.f32 "
                 "{%0,%1,%2,%3}, {%4,%5,%6,%7}, {%8,%9}, {%0,%1,%2,%3};"
                 : "+f"(c[0]), "+f"(c[1]), "+f"(c[2]), "+f"(c[3])
                 : "r"(a[0]), "r"(a[1]), "r"(a[2]), "r"(a[3]),
                   "r"(b0), "r"(b1));
}
__device__ __forceinline__ void split_pack(float x0, float x1,
                                           unsigned& wh, unsigned& wl) {
    __nv_bfloat16 h0 = __float2bfloat16_rn(x0);
    __nv_bfloat16 h1 = __float2bfloat16_rn(x1);
    float r0 = x0 - __bfloat162float(h0);
    float r1 = x1 - __bfloat162float(h1);
    __nv_bfloat16 l0 = __float2bfloat16_rn(r0);
    __nv_bfloat16 l1 = __float2bfloat16_rn(r1);
    wh = ((unsigned)__bfloat16_as_ushort(h1) << 16) | __bfloat16_as_ushort(h0);
    wl = ((unsigned)__bfloat16_as_ushort(l1) << 16) | __bfloat16_as_ushort(l0);
}

// =====================================================================
// Kernel 1: embedding/FM/LR (blocks 0..1023) + weight prep (blocks 1024+)
// =====================================================================
#define EMB_BLOCKS 1024
#define PREP_ITEMS (3 * NPAD * (KPG / 2))
#define PREP_BLOCKS ((PREP_ITEMS + 255) / 256)

__global__ __launch_bounds__(256, 1) void embed_prep_kernel(
    const int*   __restrict__ ids,
    const float* __restrict__ vals,
    const float* __restrict__ w,
    const float* __restrict__ v,
    const float* __restrict__ w0,
    const float* __restrict__ w1,
    const float* __restrict__ w2)
{
    const int tid = threadIdx.x;
    if (blockIdx.x < EMB_BLOCKS) {
        const int sub = tid >> 4;
        const int e   = tid & 15;
        const int row = blockIdx.x * 16 + sub;

        const int*   idp = ids  + row * NFEAT;
        const float* vp  = vals + row * NFEAT;

        float xv = 0.f, x2 = 0.f, lr = 0.f;
#pragma unroll
        for (int f = 0; f < NFEAT; ++f) {
            const int   id  = __ldg(idp + f);
            const float val = __ldg(vp + f);
            const float ve  = __ldg(v + (size_t)id * EMB + e);
            const float t   = val * ve;
            xv += t;
            x2 += t * t;
            if (e == 0) lr += __ldg(w + id) * val;
        }
        g_fm[row * EMB + e] = 0.5f * (xv * xv - x2);
        if (e == 0) g_lr[row] = lr;
    } else {
        const int g = (blockIdx.x - EMB_BLOCKS) * 256 + tid;
        if (g >= PREP_ITEMS) return;
        const int l   = g / (NPAD * (KPG / 2));
        const int rem = g - l * (NPAD * (KPG / 2));
        const int n   = rem / (KPG / 2);
        const int kp  = rem - n * (KPG / 2);
        const int k   = 2 * kp;
        const int Kl  = (l == 0) ? EMB : HID;
        const float* W = (l == 0) ? w0 : (l == 1) ? w1 : w2;
        float x0 = 0.f, x1 = 0.f;
        if (n < HID) {
            if (k     < Kl) x0 = __ldg(W + (size_t)k       * HID + n);
            if (k + 1 < Kl) x1 = __ldg(W + (size_t)(k + 1) * HID + n);
        }
        unsigned wh, wl;
        split_pack(x0, x1, wh, wl);
        const size_t di = ((size_t)l * NPAD + n) * KPG + k;
        *(unsigned*)((char*)g_wt_hi + di * 2) = wh;
        *(unsigned*)((char*)g_wt_lo + di * 2) = wl;
    }
}

// =====================================================================
// Kernel 2: split-bf16 mma.sync MLP. 128 rows/CTA, 512 threads (16 warps).
// Warp w: rows (w>>1)*16..+15, n-half (w&1)*104 (13 n8 tiles, 52 accs).
// =====================================================================
#define NTH2 512
#define APB  464                 // As row pitch in bytes
#define WPB  80                  // Wc row pitch in bytes
#define AS_H 0
#define AS_L (128 * APB)                     // 59392
#define WC_O (2 * 128 * APB)                 // 118784
#define WC_SZ (NPAD * WPB)                   // 16640 per buffer-half
#define BIAS_O (WC_O + 4 * WC_SZ)            // 185344
#define RSUM_O (BIAS_O + 3 * NPAD * 4)       // 187840
#define SMEM_TOT (RSUM_O + 128 * 4)          // 188352

__global__ __launch_bounds__(NTH2, 1) void mlp_mma_kernel(
    const float* __restrict__ b0,
    const float* __restrict__ b1,
    const float* __restrict__ b2,
    const float* __restrict__ bglob,
    float*       __restrict__ out)
{
    extern __shared__ char smem[];
    const uint32_t SB = smem_u32(smem);
    float* bias_s = (float*)(smem + BIAS_O);
    float* rsum_s = (float*)(smem + RSUM_O);

    const int tid  = threadIdx.x;
    const int wid  = tid >> 5;
    const int lane = tid & 31;
    const int rowgrp = wid >> 1;             // 0..7
    const int nbase  = (wid & 1) * 104;      // n-half
    const int row0 = blockIdx.x * 128;

    auto stage_lc = [](int s, int& l, int& c) {
        if (s == 0)      { l = 0; c = 0; }
        else if (s <= 7) { l = 1; c = s - 1; }
        else             { l = 2; c = s - 8; }
    };
    auto prefetch = [&](int s, int buf) {
        int l, c; stage_lc(s, l, c);
        const char* srcH = (const char*)g_wt_hi + ((size_t)l * NPAD * KPG + c * 32) * 2;
        const char* srcL = (const char*)g_wt_lo + ((size_t)l * NPAD * KPG + c * 32) * 2;
        const uint32_t dH = SB + WC_O + (uint32_t)(buf * 2 + 0) * WC_SZ;
        const uint32_t dL = SB + WC_O + (uint32_t)(buf * 2 + 1) * WC_SZ;
        for (int idx = tid; idx < NPAD * 4; idx += NTH2) {
            const int r = idx >> 2, sg = idx & 3;
            cp16(dH + r * WPB + sg * 16, srcH + (size_t)r * (KPG * 2) + sg * 16);
            cp16(dL + r * WPB + sg * 16, srcL + (size_t)r * (KPG * 2) + sg * 16);
        }
        cp_commit();
    };

    prefetch(0, 0);
    prefetch(1, 1);

    // ---- init: bias, rowsum, A-pad zero, L0 activations ----
    for (int i = tid; i < 3 * NPAD; i += NTH2) {
        const int l = i / NPAD, n = i - l * NPAD;
        const float* bp = (l == 0) ? b0 : (l == 1) ? b1 : b2;
        bias_s[i] = (n < HID) ? __ldg(bp + n) : 0.f;
    }
    if (tid < 128) rsum_s[tid] = 0.f;
    for (int i = tid; i < 128 * 8; i += NTH2) {   // zero k=208..223
        const int r = i >> 3, q = i & 7;
        *(unsigned*)(smem + AS_H + r * APB + 416 + q * 4) = 0u;
        *(unsigned*)(smem + AS_L + r * APB + 416 + q * 4) = 0u;
    }
    {
        const int r = tid >> 2;                   // 0..127
        const int q = tid & 3;                    // 4 floats each
        const float* src = g_fm + (size_t)(row0 + r) * EMB + q * 4;
        unsigned wh, wl;
        split_pack(src[0], src[1], wh, wl);
        *(unsigned*)(smem + AS_H + r * APB + q * 8)     = wh;
        *(unsigned*)(smem + AS_L + r * APB + q * 8)     = wl;
        split_pack(src[2], src[3], wh, wl);
        *(unsigned*)(smem + AS_H + r * APB + q * 8 + 4) = wh;
        *(unsigned*)(smem + AS_L + r * APB + q * 8 + 4) = wl;
    }

    float acc[13][4];
    float rs1 = 0.f, rs2 = 0.f;

    const uint32_t arow  = (uint32_t)(rowgrp * 16 + (lane & 15));
    const uint32_t akofs = (uint32_t)((lane >> 4) << 3);
    const uint32_t bnrow = (uint32_t)(nbase + (lane & 7));
    const uint32_t bk8   = (uint32_t)(((lane >> 3) & 1) << 3);

#pragma unroll 1
    for (int s = 0; s < 15; ++s) {
        int l, c; stage_lc(s, l, c);

        if (s == 0 || s == 1 || s == 8) {
#pragma unroll
            for (int t = 0; t < 13; ++t)
#pragma unroll
                for (int q = 0; q < 4; ++q) acc[t][q] = 0.f;
        }

        if (s == 14) cp_wait0(); else cp_wait1();
        __syncthreads();

        const int buf = s & 1;
        const uint32_t wbh = SB + WC_O + (uint32_t)(buf * 2 + 0) * WC_SZ;
        const uint32_t wbl = SB + WC_O + (uint32_t)(buf * 2 + 1) * WC_SZ;
        const int ksteps = (l == 0) ? 1 : 2;

#pragma unroll 1
        for (int ks = 0; ks < ksteps; ++ks) {
            const uint32_t kA = (uint32_t)((l == 0 ? 0 : c * 32) + ks * 16);
            uint32_t ah[4], al[4];
            ldsm4(SB + AS_H + arow * APB + (kA + akofs) * 2, ah);
            ldsm4(SB + AS_L + arow * APB + (kA + akofs) * 2, al);
            const uint32_t bko = (uint32_t)(ks * 16) + bk8;
            const uint32_t bhA = wbh + bnrow * WPB + bko * 2;
            const uint32_t blA = wbl + bnrow * WPB + bko * 2;
#pragma unroll
            for (int nt = 0; nt < 13; ++nt) {
                uint32_t bh[2], bl[2];
                ldsm2(bhA + nt * (8 * WPB), bh);
                ldsm2(blA + nt * (8 * WPB), bl);
                mma16816(acc[nt], ah, bh[0], bh[1]);
                mma16816(acc[nt], ah, bl[0], bl[1]);
                mma16816(acc[nt], al, bh[0], bh[1]);
            }
        }
        __syncthreads();

        if (s + 2 <= 14) prefetch(s + 2, buf);

        if (s == 0 || s == 7) {          // ReLU + re-split into As
            const int lb = (s == 0) ? 0 : 1;
            const int r1 = rowgrp * 16 + (lane >> 2);
#pragma unroll
            for (int nt = 0; nt < 13; ++nt) {
                const int n = nbase + nt * 8 + 2 * (lane & 3);
                const float bb0 = bias_s[lb * NPAD + n];
                const float bb1 = bias_s[lb * NPAD + n + 1];
                unsigned wh, wl;
                split_pack(fmaxf(acc[nt][0] + bb0, 0.f),
                           fmaxf(acc[nt][1] + bb1, 0.f), wh, wl);
                *(unsigned*)(smem + AS_H + r1 * APB + 2 * n) = wh;
                *(unsigned*)(smem + AS_L + r1 * APB + 2 * n) = wl;
                split_pack(fmaxf(acc[nt][2] + bb0, 0.f),
                           fmaxf(acc[nt][3] + bb1, 0.f), wh, wl);
                *(unsigned*)(smem + AS_H + (r1 + 8) * APB + 2 * n) = wh;
                *(unsigned*)(smem + AS_L + (r1 + 8) * APB + 2 * n) = wl;
            }
        } else if (s == 14) {            // ReLU + row-sum partials
#pragma unroll
            for (int nt = 0; nt < 13; ++nt) {
                const int n = nbase + nt * 8 + 2 * (lane & 3);
                const float bb0 = bias_s[2 * NPAD + n];
                const float bb1 = bias_s[2 * NPAD + n + 1];
                rs1 += fmaxf(acc[nt][0] + bb0, 0.f) + fmaxf(acc[nt][1] + bb1, 0.f);
                rs2 += fmaxf(acc[nt][2] + bb0, 0.f) + fmaxf(acc[nt][3] + bb1, 0.f);
            }
        }
    }

    // ---- combine row sums: reduce in 4-lane groups, then shared atomics ----
    rs1 += __shfl_xor_sync(0xffffffffu, rs1, 1);
    rs1 += __shfl_xor_sync(0xffffffffu, rs1, 2);
    rs2 += __shfl_xor_sync(0xffffffffu, rs2, 1);
    rs2 += __shfl_xor_sync(0xffffffffu, rs2, 2);
    if ((lane & 3) == 0) {
        const int r1 = rowgrp * 16 + (lane >> 2);
        atomicAdd(&rsum_s[r1],     rs1);
        atomicAdd(&rsum_s[r1 + 8], rs2);
    }
    __syncthreads();

    if (tid < 128) {
        const int gr = row0 + tid;
        const float x = g_lr[gr] + __ldg(bglob) + rsum_s[tid];
        out[gr] = 1.f / (1.f + expf(-x));
    }
}

// =====================================================================
// Launch
// =====================================================================
extern "C" void kernel_launch(void* const* d_in, const int* in_sizes, int n_in,
                              void* d_out, int out_size)
{
    const int*   feat_ids  = (const int*)  d_in[0];
    const float* feat_vals = (const float*)d_in[1];
    const float* w         = (const float*)d_in[2];
    const float* v         = (const float*)d_in[3];
    const float* b         = (const float*)d_in[4];
    const float* w0        = (const float*)d_in[5];
    const float* b0        = (const float*)d_in[6];
    const float* w1        = (const float*)d_in[7];
    const float* b1        = (const float*)d_in[8];
    const float* w2        = (const float*)d_in[9];
    const float* b2        = (const float*)d_in[10];
    float* out = (float*)d_out;

    embed_prep_kernel<<<EMB_BLOCKS + PREP_BLOCKS, 256>>>(
        feat_ids, feat_vals, w, v, w0, w1, w2);

    static bool attr_set = false;
    if (!attr_set) {
        cudaFuncSetAttribute(mlp_mma_kernel,
                             cudaFuncAttributeMaxDynamicSharedMemorySize,
                             SMEM_TOT);
        attr_set = true;
    }
    mlp_mma_kernel<<<BATCH / 128, NTH2, SMEM_TOT>>>(b0, b1, b2, b, out);
}

// round 9
// speedup vs baseline: 2.1715x; 1.2748x over previous
#include <cuda_runtime.h>
#include <cuda_bf16.h>
#include <math.h>
#include <stdint.h>

// ---------------- Problem constants ----------------
#define BATCH 16384
#define NFEAT 39
#define EMB   16
#define HID   200
#define NPAD  208           // padded N (and K) for 16/8 tiling
#define NKSG  27            // total ksteps: L0:1, L1:13, L2:13
#define NTILE 26            // n8 tiles per layer

// ---------------- Scratch ----------------
__device__ float g_fm[BATCH * EMB];
__device__ float g_lr[BATCH];
// Weights pre-packed in mma fragment order:
// [ksg (27)][ntile (26)][lane (32)] x uint4 {bh0, bh1, bl0, bl1}
__device__ uint4 g_wfrag[NKSG * NTILE * 32];

// =====================================================================
// Helpers
// =====================================================================
__device__ __forceinline__ uint32_t smem_u32(const void* p) {
    uint32_t a;
    asm("{ .reg .u64 t; cvta.to.shared.u64 t, %1; cvt.u32.u64 %0, t; }"
        : "=r"(a) : "l"(p));
    return a;
}
__device__ __forceinline__ void ldsm4(uint32_t addr, uint32_t* r) {
    asm volatile("ldmatrix.sync.aligned.m8n8.x4.shared.b16 {%0,%1,%2,%3}, [%4];"
                 : "=r"(r[0]), "=r"(r[1]), "=r"(r[2]), "=r"(r[3]) : "r"(addr));
}
__device__ __forceinline__ void mma16816(float* c, const uint32_t* a,
                                         uint32_t b0, uint32_t b1) {
    asm volatile("mma.sync.aligned.m16n8k16.row.col.f32.bf16.bf16.f32 "
                 "{%0,%1,%2,%3}, {%4,%5,%6,%7}, {%8,%9}, {%0,%1,%2,%3};"
                 : "+f"(c[0]), "+f"(c[1]), "+f"(c[2]), "+f"(c[3])
                 : "r"(a[0]), "r"(a[1]), "r"(a[2]), "r"(a[3]),
                   "r"(b0), "r"(b1));
}
__device__ __forceinline__ void split_pack(float x0, float x1,
                                           unsigned& wh, unsigned& wl) {
    __nv_bfloat16 h0 = __float2bfloat16_rn(x0);
    __nv_bfloat16 h1 = __float2bfloat16_rn(x1);
    float r0 = x0 - __bfloat162float(h0);
    float r1 = x1 - __bfloat162float(h1);
    __nv_bfloat16 l0 = __float2bfloat16_rn(r0);
    __nv_bfloat16 l1 = __float2bfloat16_rn(r1);
    wh = ((unsigned)__bfloat16_as_ushort(h1) << 16) | __bfloat16_as_ushort(h0);
    wl = ((unsigned)__bfloat16_as_ushort(l1) << 16) | __bfloat16_as_ushort(l0);
}
__device__ __forceinline__ void bar_pair(int pair) {
    asm volatile("bar.sync %0, 64;" :: "r"(1 + pair) : "memory");
}

// =====================================================================
// Kernel 1: embedding/FM/LR (blocks 0..1023) + fragment prep (blocks 1024+)
// =====================================================================
#define EMB_BLOCKS 1024
#define PREP_ITEMS (NKSG * NTILE * 32)          // 22464
#define PREP_BLOCKS ((PREP_ITEMS + 255) / 256)  // 88

__global__ __launch_bounds__(256, 1) void embed_prep_kernel(
    const int*   __restrict__ ids,
    const float* __restrict__ vals,
    const float* __restrict__ w,
    const float* __restrict__ v,
    const float* __restrict__ w0,
    const float* __restrict__ w1,
    const float* __restrict__ w2)
{
    const int tid = threadIdx.x;
    if (blockIdx.x < EMB_BLOCKS) {
        const int sub = tid >> 4;
        const int e   = tid & 15;
        const int row = blockIdx.x * 16 + sub;

        const int*   idp = ids  + row * NFEAT;
        const float* vp  = vals + row * NFEAT;

        float xv = 0.f, x2 = 0.f, lr = 0.f;
#pragma unroll
        for (int f = 0; f < NFEAT; ++f) {
            const int   id  = __ldg(idp + f);
            const float val = __ldg(vp + f);
            const float ve  = __ldg(v + (size_t)id * EMB + e);
            const float t   = val * ve;
            xv += t;
            x2 += t * t;
            if (e == 0) lr += __ldg(w + id) * val;
        }
        g_fm[row * EMB + e] = 0.5f * (xv * xv - x2);
        if (e == 0) g_lr[row] = lr;
    } else {
        const int g = (blockIdx.x - EMB_BLOCKS) * 256 + tid;
        if (g >= PREP_ITEMS) return;
        const int ksg   = g / (NTILE * 32);
        const int rem   = g - ksg * (NTILE * 32);
        const int ntile = rem >> 5;
        const int lane  = rem & 31;
        const int l  = (ksg == 0) ? 0 : (ksg <= 13) ? 1 : 2;
        const int s  = (ksg == 0) ? 0 : (ksg <= 13) ? (ksg - 1) : (ksg - 14);
        const int Kl = (l == 0) ? EMB : HID;
        const float* W = (l == 0) ? w0 : (l == 1) ? w1 : w2;

        const int n  = ntile * 8 + (lane >> 2);
        const int k0 = s * 16 + (lane & 3) * 2;

        float e0 = 0.f, e1 = 0.f, e2 = 0.f, e3 = 0.f;
        if (n < HID) {
            if (k0     < Kl) e0 = __ldg(W + (size_t)k0       * HID + n);
            if (k0 + 1 < Kl) e1 = __ldg(W + (size_t)(k0 + 1) * HID + n);
            if (k0 + 8 < Kl) e2 = __ldg(W + (size_t)(k0 + 8) * HID + n);
            if (k0 + 9 < Kl) e3 = __ldg(W + (size_t)(k0 + 9) * HID + n);
        }
        uint4 o;
        split_pack(e0, e1, o.x, o.z);
        split_pack(e2, e3, o.y, o.w);
        g_wfrag[g] = o;
    }
}

// =====================================================================
// Kernel 2: split-bf16 mma.sync MLP, B-fragments straight from L2.
// 128 rows/CTA, 512 threads (16 warps, 8 independent warp pairs).
// Warp pair p owns rows p*16..+15; warp (w&1) owns n-half.
// Only pair-local named barriers after init.
// =====================================================================
#define NTH2 512
#define APB  464                 // As row pitch in bytes (208 bf16 + pad)
#define AS_H 0
#define AS_L (128 * APB)                     // 59392
#define BIAS_O (2 * 128 * APB)               // 118784
#define RSUM_O (BIAS_O + 3 * NPAD * 4)       // 121280
#define SMEM_TOT (RSUM_O + 128 * 4)          // 121792

__global__ __launch_bounds__(NTH2, 1) void mlp_mma_kernel(
    const float* __restrict__ b0,
    const float* __restrict__ b1,
    const float* __restrict__ b2,
    const float* __restrict__ bglob,
    float*       __restrict__ out)
{
    extern __shared__ char smem[];
    const uint32_t SB = smem_u32(smem);
    float* bias_s = (float*)(smem + BIAS_O);
    float* rsum_s = (float*)(smem + RSUM_O);

    const int tid   = threadIdx.x;
    const int wid   = tid >> 5;
    const int lane  = tid & 31;
    const int pair  = wid >> 1;              // 0..7
    const int nhalf = wid & 1;
    const int nbase = nhalf * 104;
    const int row0  = blockIdx.x * 128;

    // ---- init: bias, rsum, L0 activations (per pair) ----
    for (int i = tid; i < 3 * NPAD; i += NTH2) {
        const int l = i / NPAD, n = i - l * NPAD;
        const float* bp = (l == 0) ? b0 : (l == 1) ? b1 : b2;
        bias_s[i] = (n < HID) ? __ldg(bp + n) : 0.f;
    }
    if (tid < 128) rsum_s[tid] = 0.f;
    {
        const int t64 = nhalf * 32 + lane;       // 0..63 within pair
        const int r   = pair * 16 + (t64 >> 2);  // row in CTA tile
        const int q   = t64 & 3;                 // 4 floats
        const float* src = g_fm + (size_t)(row0 + r) * EMB + q * 4;
        unsigned wh, wl;
        split_pack(src[0], src[1], wh, wl);
        *(unsigned*)(smem + AS_H + r * APB + q * 8)     = wh;
        *(unsigned*)(smem + AS_L + r * APB + q * 8)     = wl;
        split_pack(src[2], src[3], wh, wl);
        *(unsigned*)(smem + AS_H + r * APB + q * 8 + 4) = wh;
        *(unsigned*)(smem + AS_L + r * APB + q * 8 + 4) = wl;
    }
    __syncthreads();        // the only CTA-wide barrier

    float acc[13][4];
    float rs1 = 0.f, rs2 = 0.f;

    const uint32_t arow  = (uint32_t)(pair * 16 + (lane & 15));
    const uint32_t akofs = (uint32_t)((lane >> 4) << 3);
    const uint32_t aHbase = SB + AS_H + arow * APB;
    const uint32_t aLbase = SB + AS_L + arow * APB;

#pragma unroll 1
    for (int l = 0; l < 3; ++l) {
        const int ksteps = (l == 0) ? 1 : 13;
        const int ksbase = (l == 0) ? 0 : (l == 1) ? 1 : 14;

#pragma unroll
        for (int t = 0; t < 13; ++t)
#pragma unroll
            for (int q = 0; q < 4; ++q) acc[t][q] = 0.f;

#pragma unroll 1
        for (int ks = 0; ks < ksteps; ++ks) {
            const uint32_t kA = (uint32_t)(ks * 16);
            uint32_t ah[4], al[4];
            ldsm4(aHbase + (kA + akofs) * 2, ah);
            ldsm4(aLbase + (kA + akofs) * 2, al);
            const uint4* bp = g_wfrag
                + ((size_t)(ksbase + ks) * NTILE + nhalf * 13) * 32 + lane;
#pragma unroll
            for (int nt = 0; nt < 13; ++nt) {
                const uint4 f = __ldg(bp + nt * 32);
                mma16816(acc[nt], ah, f.x, f.y);   // A_hi * B_hi
                mma16816(acc[nt], ah, f.z, f.w);   // A_hi * B_lo
                mma16816(acc[nt], al, f.x, f.y);   // A_lo * B_hi
            }
        }

        if (l < 2) {
            // all reads of current As done by BOTH warps of the pair
            bar_pair(pair);
            const int r1 = pair * 16 + (lane >> 2);
#pragma unroll
            for (int nt = 0; nt < 13; ++nt) {
                const int n = nbase + nt * 8 + 2 * (lane & 3);
                const float bb0 = bias_s[l * NPAD + n];
                const float bb1 = bias_s[l * NPAD + n + 1];
                unsigned wh, wl;
                split_pack(fmaxf(acc[nt][0] + bb0, 0.f),
                           fmaxf(acc[nt][1] + bb1, 0.f), wh, wl);
                *(unsigned*)(smem + AS_H + r1 * APB + 2 * n) = wh;
                *(unsigned*)(smem + AS_L + r1 * APB + 2 * n) = wl;
                split_pack(fmaxf(acc[nt][2] + bb0, 0.f),
                           fmaxf(acc[nt][3] + bb1, 0.f), wh, wl);
                *(unsigned*)(smem + AS_H + (r1 + 8) * APB + 2 * n) = wh;
                *(unsigned*)(smem + AS_L + (r1 + 8) * APB + 2 * n) = wl;
            }
            bar_pair(pair);     // writes visible before next layer's reads
        } else {
#pragma unroll
            for (int nt = 0; nt < 13; ++nt) {
                const int n = nbase + nt * 8 + 2 * (lane & 3);
                const float bb0 = bias_s[2 * NPAD + n];
                const float bb1 = bias_s[2 * NPAD + n + 1];
                rs1 += fmaxf(acc[nt][0] + bb0, 0.f) + fmaxf(acc[nt][1] + bb1, 0.f);
                rs2 += fmaxf(acc[nt][2] + bb0, 0.f) + fmaxf(acc[nt][3] + bb1, 0.f);
            }
        }
    }

    // ---- row sums: 4-lane shfl reduce, pair-shared atomics, pair barrier ----
    rs1 += __shfl_xor_sync(0xffffffffu, rs1, 1);
    rs1 += __shfl_xor_sync(0xffffffffu, rs1, 2);
    rs2 += __shfl_xor_sync(0xffffffffu, rs2, 1);
    rs2 += __shfl_xor_sync(0xffffffffu, rs2, 2);
    if ((lane & 3) == 0) {
        const int r1 = pair * 16 + (lane >> 2);
        atomicAdd(&rsum_s[r1],     rs1);
        atomicAdd(&rsum_s[r1 + 8], rs2);
    }
    bar_pair(pair);

    if (nhalf == 0 && lane < 16) {
        const int r  = pair * 16 + lane;
        const int gr = row0 + r;
        const float x = g_lr[gr] + __ldg(bglob) + rsum_s[r];
        out[gr] = 1.f / (1.f + expf(-x));
    }
}

// =====================================================================
// Launch
// =====================================================================
extern "C" void kernel_launch(void* const* d_in, const int* in_sizes, int n_in,
                              void* d_out, int out_size)
{
    const int*   feat_ids  = (const int*)  d_in[0];
    const float* feat_vals = (const float*)d_in[1];
    const float* w         = (const float*)d_in[2];
    const float* v         = (const float*)d_in[3];
    const float* b         = (const float*)d_in[4];
    const float* w0        = (const float*)d_in[5];
    const float* b0        = (const float*)d_in[6];
    const float* w1        = (const float*)d_in[7];
    const float* b1        = (const float*)d_in[8];
    const float* w2        = (const float*)d_in[9];
    const float* b2        = (const float*)d_in[10];
    float* out = (float*)d_out;

    embed_prep_kernel<<<EMB_BLOCKS + PREP_BLOCKS, 256>>>(
        feat_ids, feat_vals, w, v, w0, w1, w2);

    static bool attr_set = false;
    if (!attr_set) {
        cudaFuncSetAttribute(mlp_mma_kernel,
                             cudaFuncAttributeMaxDynamicSharedMemorySize,
                             SMEM_TOT);
        attr_set = true;
    }
    mlp_mma_kernel<<<BATCH / 128, NTH2, SMEM_TOT>>>(b0, b1, b2, b, out);
}

// round 11
// speedup vs baseline: 2.4859x; 1.1448x over previous
#include <cuda_runtime.h>
#include <cuda_bf16.h>
#include <math.h>
#include <stdint.h>

// ---------------- Problem constants ----------------
#define BATCH 16384
#define NFEAT 39
#define EMB   16
#define HID   200
#define NPAD  208           // padded N (and K) for 16/8 tiling
#define NKSG  27            // total ksteps: L0:1, L1:13, L2:13
#define NTILE 26            // n8 tiles per layer

// ---------------- Scratch ----------------
// Weights pre-packed in mma fragment order:
// [ksg (27)][ntile (26)][lane (32)] x uint4 {bh0, bh1, bl0, bl1}
__device__ uint4 g_wfrag[NKSG * NTILE * 32];

// =====================================================================
// Helpers
// =====================================================================
__device__ __forceinline__ uint32_t smem_u32(const void* p) {
    uint32_t a;
    asm("{ .reg .u64 t; cvta.to.shared.u64 t, %1; cvt.u32.u64 %0, t; }"
        : "=r"(a) : "l"(p));
    return a;
}
__device__ __forceinline__ void ldsm4(uint32_t addr, uint32_t* r) {
    asm volatile("ldmatrix.sync.aligned.m8n8.x4.shared.b16 {%0,%1,%2,%3}, [%4];"
                 : "=r"(r[0]), "=r"(r[1]), "=r"(r[2]), "=r"(r[3]) : "r"(addr));
}
__device__ __forceinline__ void mma16816(float* c, const uint32_t* a,
                                         uint32_t b0, uint32_t b1) {
    asm volatile("mma.sync.aligned.m16n8k16.row.col.f32.bf16.bf16.f32 "
                 "{%0,%1,%2,%3}, {%4,%5,%6,%7}, {%8,%9}, {%0,%1,%2,%3};"
                 : "+f"(c[0]), "+f"(c[1]), "+f"(c[2]), "+f"(c[3])
                 : "r"(a[0]), "r"(a[1]), "r"(a[2]), "r"(a[3]),
                   "r"(b0), "r"(b1));
}
__device__ __forceinline__ void split_pack(float x0, float x1,
                                           unsigned& wh, unsigned& wl) {
    __nv_bfloat16 h0 = __float2bfloat16_rn(x0);
    __nv_bfloat16 h1 = __float2bfloat16_rn(x1);
    float r0 = x0 - __bfloat162float(h0);
    float r1 = x1 - __bfloat162float(h1);
    __nv_bfloat16 l0 = __float2bfloat16_rn(r0);
    __nv_bfloat16 l1 = __float2bfloat16_rn(r1);
    wh = ((unsigned)__bfloat16_as_ushort(h1) << 16) | __bfloat16_as_ushort(h0);
    wl = ((unsigned)__bfloat16_as_ushort(l1) << 16) | __bfloat16_as_ushort(l0);
}
__device__ __forceinline__ void bar_pair(int pair) {
    asm volatile("bar.sync %0, 64;" :: "r"(1 + pair) : "memory");
}

// =====================================================================
// Kernel 1: weight fragment prep only (small, fast)
// =====================================================================
#define PREP_ITEMS (NKSG * NTILE * 32)          // 22464
#define PREP_BLOCKS ((PREP_ITEMS + 255) / 256)  // 88

__global__ __launch_bounds__(256, 1) void prep_kernel(
    const float* __restrict__ w0,
    const float* __restrict__ w1,
    const float* __restrict__ w2)
{
    const int g = blockIdx.x * 256 + threadIdx.x;
    if (g >= PREP_ITEMS) return;
    const int ksg   = g / (NTILE * 32);
    const int rem   = g - ksg * (NTILE * 32);
    const int ntile = rem >> 5;
    const int lane  = rem & 31;
    const int l  = (ksg == 0) ? 0 : (ksg <= 13) ? 1 : 2;
    const int s  = (ksg == 0) ? 0 : (ksg <= 13) ? (ksg - 1) : (ksg - 14);
    const int Kl = (l == 0) ? EMB : HID;
    const float* W = (l == 0) ? w0 : (l == 1) ? w1 : w2;

    const int n  = ntile * 8 + (lane >> 2);
    const int k0 = s * 16 + (lane & 3) * 2;

    float e0 = 0.f, e1 = 0.f, e2 = 0.f, e3 = 0.f;
    if (n < HID) {
        if (k0     < Kl) e0 = __ldg(W + (size_t)k0       * HID + n);
        if (k0 + 1 < Kl) e1 = __ldg(W + (size_t)(k0 + 1) * HID + n);
        if (k0 + 8 < Kl) e2 = __ldg(W + (size_t)(k0 + 8) * HID + n);
        if (k0 + 9 < Kl) e3 = __ldg(W + (size_t)(k0 + 9) * HID + n);
    }
    uint4 o;
    split_pack(e0, e1, o.x, o.z);
    split_pack(e2, e3, o.y, o.w);
    g_wfrag[g] = o;
}

// =====================================================================
// Kernel 2: fused embed + FM + split-bf16 mma.sync MLP + sigmoid.
// 64 rows/CTA, 256 threads (8 warps, 4 independent 64-thread pairs),
// 2 CTAs/SM. Pair p owns rows p*16..+15; warp (w&1) owns an n-half.
// B fragments straight from L1/L2 (shared across all warps on the SM).
// =====================================================================
#define NTH2 256
#define ROWS 64
#define APB  464                 // As row pitch in bytes (208 bf16 + pad)
#define AS_H 0
#define AS_L (ROWS * APB)                    // 29696
#define BIAS_O (2 * ROWS * APB)              // 59392
#define RSUM_O (BIAS_O + 3 * NPAD * 4)       // 61888
#define LR_O   (RSUM_O + ROWS * 4)           // 62144
#define SMEM_TOT (LR_O + ROWS * 4)           // 62400

__global__ __launch_bounds__(NTH2, 2) void nfm_fused_kernel(
    const int*   __restrict__ ids,
    const float* __restrict__ vals,
    const float* __restrict__ w,
    const float* __restrict__ v,
    const float* __restrict__ b0,
    const float* __restrict__ b1,
    const float* __restrict__ b2,
    const float* __restrict__ bglob,
    float*       __restrict__ out)
{
    extern __shared__ char smem[];
    const uint32_t SB = smem_u32(smem);
    float* bias_s = (float*)(smem + BIAS_O);
    float* rsum_s = (float*)(smem + RSUM_O);
    float* lr_s   = (float*)(smem + LR_O);

    const int tid   = threadIdx.x;
    const int wid   = tid >> 5;
    const int lane  = tid & 31;
    const int pair  = wid >> 1;              // 0..3
    const int nhalf = wid & 1;
    const int nbase = nhalf * 104;
    const int row0  = blockIdx.x * ROWS;

    // ---- init: bias + rsum (CTA-wide, once) ----
    for (int i = tid; i < 3 * NPAD; i += NTH2) {
        const int l = i / NPAD, n = i - l * NPAD;
        const float* bp = (l == 0) ? b0 : (l == 1) ? b1 : b2;
        bias_s[i] = (n < HID) ? __ldg(bp + n) : 0.f;
    }
    if (tid < ROWS) rsum_s[tid] = 0.f;
    __syncthreads();        // the only CTA-wide barrier

    // ---- fused embedding gather + FM (pair-local: 16 rows per pair) ----
    {
        const int t64 = nhalf * 32 + lane;   // 0..63 within pair
        const int hw  = t64 >> 4;            // half-warp slot 0..3
        const int e   = t64 & 15;            // embedding dim
#pragma unroll 1
        for (int pass = 0; pass < 4; ++pass) {
            const int r  = pair * 16 + 4 * pass + hw;
            const int gr = row0 + r;
            const int*   idp = ids  + gr * NFEAT;
            const float* vp  = vals + gr * NFEAT;
            float xv = 0.f, x2 = 0.f, lr = 0.f;
#pragma unroll
            for (int f = 0; f < NFEAT; ++f) {
                const int   id  = __ldg(idp + f);
                const float val = __ldg(vp + f);
                const float ve  = __ldg(v + (size_t)id * EMB + e);
                const float t   = val * ve;
                xv += t;
                x2 += t * t;
                if (e == 0) lr += __ldg(w + id) * val;
            }
            const float fmv = 0.5f * (xv * xv - x2);
            const float nbv = __shfl_down_sync(0xffffffffu, fmv, 1, 16);
            if ((e & 1) == 0) {
                unsigned wh, wl;
                split_pack(fmv, nbv, wh, wl);
                *(unsigned*)(smem + AS_H + r * APB + 2 * e) = wh;
                *(unsigned*)(smem + AS_L + r * APB + 2 * e) = wl;
            }
            if (e == 0) lr_s[r] = lr;
        }
    }
    bar_pair(pair);          // this pair's 16 rows of As are ready

    float acc[13][4];
    float rs1 = 0.f, rs2 = 0.f;

    const uint32_t arow  = (uint32_t)(pair * 16 + (lane & 15));
    const uint32_t akofs = (uint32_t)((lane >> 4) << 3);
    const uint32_t aHbase = SB + AS_H + arow * APB;
    const uint32_t aLbase = SB + AS_L + arow * APB;

#pragma unroll 1
    for (int l = 0; l < 3; ++l) {
        const int ksteps = (l == 0) ? 1 : 13;
        const int ksbase = (l == 0) ? 0 : (l == 1) ? 1 : 14;

#pragma unroll
        for (int t = 0; t < 13; ++t)
#pragma unroll
            for (int q = 0; q < 4; ++q) acc[t][q] = 0.f;

#pragma unroll 1
        for (int ks = 0; ks < ksteps; ++ks) {
            const uint32_t kA = (uint32_t)(ks * 16);
            uint32_t ah[4], al[4];
            ldsm4(aHbase + (kA + akofs) * 2, ah);
            ldsm4(aLbase + (kA + akofs) * 2, al);
            const uint4* bp = g_wfrag
                + ((size_t)(ksbase + ks) * NTILE + nhalf * 13) * 32 + lane;
#pragma unroll
            for (int nt = 0; nt < 13; ++nt) {
                const uint4 f = __ldg(bp + nt * 32);
                mma16816(acc[nt], ah, f.x, f.y);   // A_hi * B_hi
                mma16816(acc[nt], ah, f.z, f.w);   // A_hi * B_lo
                mma16816(acc[nt], al, f.x, f.y);   // A_lo * B_hi
            }
        }

        if (l < 2) {
            bar_pair(pair);  // both warps of pair done reading As
            const int r1 = pair * 16 + (lane >> 2);
#pragma unroll
            for (int nt = 0; nt < 13; ++nt) {
                const int n = nbase + nt * 8 + 2 * (lane & 3);
                const float bb0 = bias_s[l * NPAD + n];
                const float bb1 = bias_s[l * NPAD + n + 1];
                unsigned wh, wl;
                split_pack(fmaxf(acc[nt][0] + bb0, 0.f),
                           fmaxf(acc[nt][1] + bb1, 0.f), wh, wl);
                *(unsigned*)(smem + AS_H + r1 * APB + 2 * n) = wh;
                *(unsigned*)(smem + AS_L + r1 * APB + 2 * n) = wl;
                split_pack(fmaxf(acc[nt][2] + bb0, 0.f),
                           fmaxf(acc[nt][3] + bb1, 0.f), wh, wl);
                *(unsigned*)(smem + AS_H + (r1 + 8) * APB + 2 * n) = wh;
                *(unsigned*)(smem + AS_L + (r1 + 8) * APB + 2 * n) = wl;
            }
            bar_pair(pair);  // writes visible before next layer's reads
        } else {
#pragma unroll
            for (int nt = 0; nt < 13; ++nt) {
                const int n = nbase + nt * 8 + 2 * (lane & 3);
                const float bb0 = bias_s[2 * NPAD + n];
                const float bb1 = bias_s[2 * NPAD + n + 1];
                rs1 += fmaxf(acc[nt][0] + bb0, 0.f) + fmaxf(acc[nt][1] + bb1, 0.f);
                rs2 += fmaxf(acc[nt][2] + bb0, 0.f) + fmaxf(acc[nt][3] + bb1, 0.f);
            }
        }
    }

    // ---- row sums: 4-lane shfl reduce, pair-shared atomics, pair barrier ----
    rs1 += __shfl_xor_sync(0xffffffffu, rs1, 1);
    rs1 += __shfl_xor_sync(0xffffffffu, rs1, 2);
    rs2 += __shfl_xor_sync(0xffffffffu, rs2, 1);
    rs2 += __shfl_xor_sync(0xffffffffu, rs2, 2);
    if ((lane & 3) == 0) {
        const int r1 = pair * 16 + (lane >> 2);
        atomicAdd(&rsum_s[r1],     rs1);
        atomicAdd(&rsum_s[r1 + 8], rs2);
    }
    bar_pair(pair);

    if (nhalf == 0 && lane < 16) {
        const int r  = pair * 16 + lane;
        const int gr = row0 + r;
        const float x = lr_s[r] + __ldg(bglob) + rsum_s[r];
        out[gr] = 1.f / (1.f + expf(-x));
    }
}

// =====================================================================
// Launch
// =====================================================================
extern "C" void kernel_launch(void* const* d_in, const int* in_sizes, int n_in,
                              void* d_out, int out_size)
{
    const int*   feat_ids  = (const int*)  d_in[0];
    const float* feat_vals = (const float*)d_in[1];
    const float* w         = (const float*)d_in[2];
    const float* v         = (const float*)d_in[3];
    const float* b         = (const float*)d_in[4];
    const float* w0        = (const float*)d_in[5];
    const float* b0        = (const float*)d_in[6];
    const float* w1        = (const float*)d_in[7];
    const float* b1        = (const float*)d_in[8];
    const float* w2        = (const float*)d_in[9];
    const float* b2        = (const float*)d_in[10];
    float* out = (float*)d_out;

    prep_kernel<<<PREP_BLOCKS, 256>>>(w0, w1, w2);

    static bool attr_set = false;
    if (!attr_set) {
        cudaFuncSetAttribute(nfm_fused_kernel,
                             cudaFuncAttributeMaxDynamicSharedMemorySize,
                             SMEM_TOT);
        attr_set = true;
    }
    nfm_fused_kernel<<<BATCH / ROWS, NTH2, SMEM_TOT>>>(
        feat_ids, feat_vals, w, v, b0, b1, b2, b, out);
}